// round 8
// baseline (speedup 1.0000x reference)
#include <cuda_runtime.h>
#include <cuda_bf16.h>
#include <cstdint>

#define T_ 512
#define B_ 64
#define I_ 512
#define H_ 512

// ---------------- scratch (static device globals; no allocation allowed) ----
__device__ float g_xproj[2][T_][B_][H_];   // input projections per dir
__device__ float g_hx[2][2][B_][H_];       // h exchange, double-buffered by parity
__device__ int   g_flag[2][8][8];          // per (dir, batch-group, cta) step flags (monotonic)

// ---------------- Phase 1: xproj GEMM via mma.sync bf16 hi/lo ---------------
// C[m][n] = sum_k x[m][k]*W[n][k] + bias[n]. M=32768 (t,b), N=512, K=512/dir.
// fp32 -> bf16 hi + bf16 lo; D += Ahi*Bhi + Ahi*Blo + Alo*Bhi (fp32 acc).
// CTA tile 128M x 64N, 256 thr (8 warps as 4Mx2N, warp tile 32x32).
// K staged in chunks of 64 into SMEM (bf16, row pitch 72 = conflict-free).

#define APITCH 144                 // bytes per A/B smem row (72 bf16)
#define XA_BYTES (128 * APITCH)    // 18432
#define XB_BYTES (64 * APITCH)     // 9216
#define XP_SMEM  (2 * XA_BYTES + 2 * XB_BYTES)   // 55296

__device__ __forceinline__ void cvt_split(float4 v, uint2& hi, uint2& lo) {
    __nv_bfloat162 h01 = __float22bfloat162_rn(make_float2(v.x, v.y));
    __nv_bfloat162 h23 = __float22bfloat162_rn(make_float2(v.z, v.w));
    float2 f01 = __bfloat1622float2(h01);
    float2 f23 = __bfloat1622float2(h23);
    __nv_bfloat162 l01 = __float22bfloat162_rn(make_float2(v.x - f01.x, v.y - f01.y));
    __nv_bfloat162 l23 = __float22bfloat162_rn(make_float2(v.z - f23.x, v.w - f23.y));
    hi.x = *(uint32_t*)&h01; hi.y = *(uint32_t*)&h23;
    lo.x = *(uint32_t*)&l01; lo.y = *(uint32_t*)&l23;
}

__device__ __forceinline__ void mma16816(float* c,
    uint32_t a0, uint32_t a1, uint32_t a2, uint32_t a3,
    uint32_t b0, uint32_t b1)
{
    asm volatile(
        "mma.sync.aligned.m16n8k16.row.col.f32.bf16.bf16.f32 "
        "{%0,%1,%2,%3}, {%4,%5,%6,%7}, {%8,%9}, {%0,%1,%2,%3};"
        : "+f"(c[0]), "+f"(c[1]), "+f"(c[2]), "+f"(c[3])
        : "r"(a0), "r"(a1), "r"(a2), "r"(a3), "r"(b0), "r"(b1));
}

__global__ void __launch_bounds__(256, 1) xproj_mma_kernel(
    const float* __restrict__ x,
    const float* __restrict__ Wf, const float* __restrict__ bf,
    const float* __restrict__ Wb, const float* __restrict__ bb)
{
    extern __shared__ __align__(16) char smem[];
    char* Ahi = smem;
    char* Alo = smem + XA_BYTES;
    char* Bhi = smem + 2 * XA_BYTES;
    char* Blo = smem + 2 * XA_BYTES + XB_BYTES;

    const int tid  = threadIdx.x;
    const int wid  = tid >> 5;
    const int lane = tid & 31;
    const int wm   = wid >> 1;          // 0..3 (M)
    const int wn   = wid & 1;           // 0..1 (N)
    const int laneR = lane >> 2;        // 0..7
    const int laneC = lane & 3;         // 0..3

    const int dir = blockIdx.z;
    const int n0  = blockIdx.x * 64;
    const int m0  = blockIdx.y * 128;
    const float* __restrict__ W    = dir ? Wb : Wf;
    const float* __restrict__ bias = dir ? bb : bf;
    float* __restrict__ out = &g_xproj[dir][0][0][0];

    // staging maps
    const int arow = tid >> 1;               // 0..127
    const int acS  = (tid & 1) * 32;         // k base within 64-chunk
    const int brow = tid >> 2;               // 0..63
    const int bcS  = (tid & 3) * 16;
    const float* __restrict__ xr = x + (size_t)(m0 + arow) * I_ + acS;
    const float* __restrict__ wr = W + (size_t)(n0 + brow) * I_ + bcS;

    float acc[2][4][4];
#pragma unroll
    for (int mi = 0; mi < 2; mi++)
#pragma unroll
        for (int ni = 0; ni < 4; ni++)
#pragma unroll
            for (int q = 0; q < 4; q++) acc[mi][ni][q] = 0.f;

    float4 aR[8], bR[4];
#pragma unroll
    for (int i = 0; i < 8; i++) aR[i] = *(const float4*)(xr + i * 4);
#pragma unroll
    for (int i = 0; i < 4; i++) bR[i] = *(const float4*)(wr + i * 4);

    const int aBase = (wm * 32 + laneR) * APITCH + laneC * 4;
    const int bBase = (wn * 32 + laneR) * APITCH + laneC * 4;

    for (int st = 0; st < 8; st++) {
        // store staged chunk (bf16 hi/lo)
#pragma unroll
        for (int i = 0; i < 8; i++) {
            uint2 h, l; cvt_split(aR[i], h, l);
            int off = arow * APITCH + (acS + i * 4) * 2;
            *(uint2*)(Ahi + off) = h;
            *(uint2*)(Alo + off) = l;
        }
#pragma unroll
        for (int i = 0; i < 4; i++) {
            uint2 h, l; cvt_split(bR[i], h, l);
            int off = brow * APITCH + (bcS + i * 4) * 2;
            *(uint2*)(Bhi + off) = h;
            *(uint2*)(Blo + off) = l;
        }
        __syncthreads();

        if (st < 7) {  // prefetch next chunk under the MMAs
            const float* xr2 = xr + (st + 1) * 64;
            const float* wr2 = wr + (st + 1) * 64;
#pragma unroll
            for (int i = 0; i < 8; i++) aR[i] = *(const float4*)(xr2 + i * 4);
#pragma unroll
            for (int i = 0; i < 4; i++) bR[i] = *(const float4*)(wr2 + i * 4);
        }

#pragma unroll
        for (int kb = 0; kb < 64; kb += 16) {
            uint32_t bh[4][2], bl[4][2];
#pragma unroll
            for (int ni = 0; ni < 4; ni++) {
                int boff = bBase + ni * 8 * APITCH + kb * 2;
                bh[ni][0] = *(const uint32_t*)(Bhi + boff);
                bh[ni][1] = *(const uint32_t*)(Bhi + boff + 16);
                bl[ni][0] = *(const uint32_t*)(Blo + boff);
                bl[ni][1] = *(const uint32_t*)(Blo + boff + 16);
            }
#pragma unroll
            for (int mi = 0; mi < 2; mi++) {
                int aoff = aBase + mi * 16 * APITCH + kb * 2;
                uint32_t ah0 = *(const uint32_t*)(Ahi + aoff);
                uint32_t ah1 = *(const uint32_t*)(Ahi + aoff + 8 * APITCH);
                uint32_t ah2 = *(const uint32_t*)(Ahi + aoff + 16);
                uint32_t ah3 = *(const uint32_t*)(Ahi + aoff + 8 * APITCH + 16);
                uint32_t al0 = *(const uint32_t*)(Alo + aoff);
                uint32_t al1 = *(const uint32_t*)(Alo + aoff + 8 * APITCH);
                uint32_t al2 = *(const uint32_t*)(Alo + aoff + 16);
                uint32_t al3 = *(const uint32_t*)(Alo + aoff + 8 * APITCH + 16);
#pragma unroll
                for (int ni = 0; ni < 4; ni++) {
                    mma16816(acc[mi][ni], ah0, ah1, ah2, ah3, bh[ni][0], bh[ni][1]);
                    mma16816(acc[mi][ni], ah0, ah1, ah2, ah3, bl[ni][0], bl[ni][1]);
                    mma16816(acc[mi][ni], al0, al1, al2, al3, bh[ni][0], bh[ni][1]);
                }
            }
        }
        __syncthreads();
    }

    // epilogue: D rows -> (t, b), cols -> j; add bias
#pragma unroll
    for (int mi = 0; mi < 2; mi++) {
#pragma unroll
        for (int ni = 0; ni < 4; ni++) {
            const int j = n0 + wn * 32 + ni * 8 + laneC * 2;
            float2 bv = *(const float2*)(bias + j);
            int m1 = m0 + wm * 32 + mi * 16 + laneR;
            int t1 = m1 & 511, b1 = m1 >> 9;
            float2 o1;
            o1.x = acc[mi][ni][0] + bv.x;
            o1.y = acc[mi][ni][1] + bv.y;
            *(float2*)(out + ((size_t)t1 * B_ + b1) * H_ + j) = o1;
            int m2 = m1 + 8;
            int t2 = m2 & 511, b2 = m2 >> 9;
            float2 o2;
            o2.x = acc[mi][ni][2] + bv.x;
            o2.y = acc[mi][ni][3] + bv.y;
            *(float2*)(out + ((size_t)t2 * B_ + b2) * H_ + j) = o2;
        }
    }
}

// ---------------- Phase 2: persistent recurrence (j-split, no reduction) ----
// 128 CTAs = 2 dirs x 8 batch-groups x 8 j-slice CTAs. Each CTA holds its
// 64x512 Wh slice (row-major, padded) + h state for 8 batches in SMEM.
// Warp w owns j-columns w*4..w*4+3 for all 8 batches; each lane owns ONE
// output (b = lane>>2, jl = lane&3) and computes the full K=512 dot product
// with 4 independent partial accumulators (ILP for the FFMA pipe).

#define WPAD 516                           // row pad: +4 banks stagger
#define SMEM_WHS2  (64 * WPAD)
#define SMEM_HCUR2 (8 * WPAD)
#define SMEM_BYTES ((SMEM_WHS2 + SMEM_HCUR2) * 4)   // 148,608 B

__global__ void __launch_bounds__(512, 1) rnn_kernel(
    const float* __restrict__ h0f, const float* __restrict__ h0b,
    const float* __restrict__ Whf, const float* __restrict__ Whb,
    float* __restrict__ y, float* __restrict__ hTf, float* __restrict__ hTb)
{
    extern __shared__ __align__(16) float smemf[];
    float* Whs  = smemf;                    // [64][516]
    float* hcur = smemf + SMEM_WHS2;        // [8][516]

    const int tid = threadIdx.x;
    const int c   = blockIdx.x & 7;
    const int grp = blockIdx.x >> 3;
    const int dir = grp >> 3;
    const int bg  = grp & 7;
    const int b0  = bg * 8;
    const int j0  = c * 64;

    const float* __restrict__ Wh = dir ? Whb : Whf;
    const float* __restrict__ h0 = dir ? h0b : h0f;
    const float* __restrict__ xp_base = &g_xproj[dir][0][0][0];
    float* __restrict__ hxd = &g_hx[dir][0][0][0];
    int* flags = &g_flag[dir][bg][0];

    // monotonic flag base (flags persist across graph replays)
    int base;
    asm volatile("ld.global.cg.u32 %0, [%1];" : "=r"(base) : "l"(&flags[c]));

    // Wh slice, row-major padded: Whs[jj][k]
    for (int idx = tid; idx < 64 * 512; idx += 512) {
        int jj = idx >> 9;          // 0..63
        int k  = idx & 511;         // == tid
        Whs[jj * WPAD + k] = Wh[(size_t)(j0 + jj) * H_ + k];
    }
    // initial h, padded layout
    {
        const float4* src = (const float4*)(h0 + (size_t)b0 * H_);
#pragma unroll
        for (int i = 0; i < 2; i++) {
            int f  = tid + i * 512;        // 0..1023 float4s
            int b  = f >> 7;
            int k4 = f & 127;
            *(float4*)&hcur[b * WPAD + k4 * 4] = src[f];
        }
    }
    __syncthreads();

    const int lane = tid & 31;
    const int w    = tid >> 5;          // 16 warps
    const int b    = lane >> 2;         // 0..7
    const int jl   = lane & 3;
    const int jj   = w * 4 + jl;        // 0..63
    const int j    = j0 + jj;

    const float4* wp = (const float4*)&Whs[jj * WPAD];
    const float4* hp = (const float4*)&hcur[b * WPAD];
    float* yrow  = y + ((size_t)(b0 + b) * T_) * (2 * H_) + dir * H_ + j;
    float* hTrow = (dir ? hTb : hTf) + (size_t)(b0 + b) * H_ + j;

    for (int s = 0; s < T_; s++) {
        const int t = dir ? (T_ - 1 - s) : s;

        // issue xp load early; hidden under the 4096-cyc dot product
        float xpv = xp_base[((size_t)t * B_ + b0 + b) * H_ + j];

        float a0 = 0.f, a1 = 0.f, a2 = 0.f, a3 = 0.f;
#pragma unroll 8
        for (int k4 = 0; k4 < 128; k4 += 4) {
            float4 w0 = wp[k4 + 0], h0v = hp[k4 + 0];
            float4 w1 = wp[k4 + 1], h1v = hp[k4 + 1];
            float4 w2 = wp[k4 + 2], h2v = hp[k4 + 2];
            float4 w3 = wp[k4 + 3], h3v = hp[k4 + 3];
            a0 += w0.x * h0v.x; a0 += w0.y * h0v.y; a0 += w0.z * h0v.z; a0 += w0.w * h0v.w;
            a1 += w1.x * h1v.x; a1 += w1.y * h1v.y; a1 += w1.z * h1v.z; a1 += w1.w * h1v.w;
            a2 += w2.x * h2v.x; a2 += w2.y * h2v.y; a2 += w2.z * h2v.z; a2 += w2.w * h2v.w;
            a3 += w3.x * h3v.x; a3 += w3.y * h3v.y; a3 += w3.z * h3v.z; a3 += w3.w * h3v.w;
        }
        float hn = tanhf(xpv + ((a0 + a1) + (a2 + a3)));

        const int p2 = (s + 1) & 1;
        yrow[(size_t)t * (2 * H_)] = hn;
        __stcg(&hxd[((size_t)p2 * B_ + b0 + b) * H_ + j], hn);
        if (s == T_ - 1) *hTrow = hn;

        __threadfence();
        __syncthreads();
        if (tid == 0) atomicExch(&flags[c], base + s + 1);

        if (tid < 8) {
            const int target = base + s + 1;
            int fv;
            do {
                asm volatile("ld.global.cg.u32 %0, [%1];" : "=r"(fv) : "l"(&flags[tid]));
                if (fv - target >= 0) break;
                __nanosleep(64);
            } while (true);
        }
        __syncthreads();

        // reload full h for our 8 batches (padded layout)
        {
            const float4* src = (const float4*)&hxd[((size_t)p2 * B_ + b0) * H_];
#pragma unroll
            for (int i = 0; i < 2; i++) {
                int f  = tid + i * 512;
                int bb = f >> 7;
                int k4 = f & 127;
                float4 v = __ldcg(&src[f]);
                *(float4*)&hcur[bb * WPAD + k4 * 4] = v;
            }
        }
        __syncthreads();
    }
}

// ---------------- launch -----------------------------------------------------
extern "C" void kernel_launch(void* const* d_in, const int* in_sizes, int n_in,
                              void* d_out, int out_size)
{
    (void)in_sizes; (void)n_in; (void)out_size;
    const float* x   = (const float*)d_in[0];
    const float* h0f = (const float*)d_in[1];
    const float* h0b = (const float*)d_in[2];
    const float* Wxf = (const float*)d_in[3];
    const float* bxf = (const float*)d_in[4];
    const float* Whf = (const float*)d_in[5];
    const float* Wxb = (const float*)d_in[6];
    const float* bxb = (const float*)d_in[7];
    const float* Whb = (const float*)d_in[8];

    float* y   = (float*)d_out;                       // (B, T, 2H)
    float* hTf = y + (size_t)B_ * T_ * 2 * H_;        // (B, H)
    float* hTb = hTf + (size_t)B_ * H_;               // (B, H)

    cudaFuncSetAttribute(xproj_mma_kernel, cudaFuncAttributeMaxDynamicSharedMemorySize,
                         XP_SMEM);
    cudaFuncSetAttribute(rnn_kernel, cudaFuncAttributeMaxDynamicSharedMemorySize,
                         SMEM_BYTES);

    dim3 gg(8, 256, 2);   // N/64, M/128, dir
    xproj_mma_kernel<<<gg, 256, XP_SMEM>>>(x, Wxf, bxf, Wxb, bxb);

    rnn_kernel<<<128, 512, SMEM_BYTES>>>(h0f, h0b, Whf, Whb, y, hTf, hTb);
}

// round 12
// speedup vs baseline: 1.8147x; 1.8147x over previous
#include <cuda_runtime.h>
#include <cuda_bf16.h>
#include <cstdint>

#define T_ 512
#define B_ 64
#define I_ 512
#define H_ 512

// ---------------- scratch (static device globals; no allocation allowed) ----
__device__ float g_xproj[2][T_][B_][H_];   // input projections per dir
__device__ float g_hx[2][2][B_][H_];       // h exchange, double-buffered by parity
__device__ int   g_flag[2][8][8];          // per (dir, batch-group, cta) step flags (monotonic)

// ---------------- Phase 1: xproj GEMM via mma.sync bf16 hi/lo (validated) ---
#define APITCH 144                 // bytes per A/B smem row (72 bf16)
#define XA_BYTES (128 * APITCH)    // 18432
#define XB_BYTES (64 * APITCH)     // 9216
#define XP_SMEM  (2 * XA_BYTES + 2 * XB_BYTES)   // 55296

__device__ __forceinline__ void cvt_split(float4 v, uint2& hi, uint2& lo) {
    __nv_bfloat162 h01 = __float22bfloat162_rn(make_float2(v.x, v.y));
    __nv_bfloat162 h23 = __float22bfloat162_rn(make_float2(v.z, v.w));
    float2 f01 = __bfloat1622float2(h01);
    float2 f23 = __bfloat1622float2(h23);
    __nv_bfloat162 l01 = __float22bfloat162_rn(make_float2(v.x - f01.x, v.y - f01.y));
    __nv_bfloat162 l23 = __float22bfloat162_rn(make_float2(v.z - f23.x, v.w - f23.y));
    hi.x = *(uint32_t*)&h01; hi.y = *(uint32_t*)&h23;
    lo.x = *(uint32_t*)&l01; lo.y = *(uint32_t*)&l23;
}

__device__ __forceinline__ void mma16816(float* c,
    uint32_t a0, uint32_t a1, uint32_t a2, uint32_t a3,
    uint32_t b0, uint32_t b1)
{
    asm volatile(
        "mma.sync.aligned.m16n8k16.row.col.f32.bf16.bf16.f32 "
        "{%0,%1,%2,%3}, {%4,%5,%6,%7}, {%8,%9}, {%0,%1,%2,%3};"
        : "+f"(c[0]), "+f"(c[1]), "+f"(c[2]), "+f"(c[3])
        : "r"(a0), "r"(a1), "r"(a2), "r"(a3), "r"(b0), "r"(b1));
}

__global__ void __launch_bounds__(256, 1) xproj_mma_kernel(
    const float* __restrict__ x,
    const float* __restrict__ Wf, const float* __restrict__ bf,
    const float* __restrict__ Wb, const float* __restrict__ bb)
{
    extern __shared__ __align__(16) char smem[];
    char* Ahi = smem;
    char* Alo = smem + XA_BYTES;
    char* Bhi = smem + 2 * XA_BYTES;
    char* Blo = smem + 2 * XA_BYTES + XB_BYTES;

    const int tid  = threadIdx.x;
    const int wid  = tid >> 5;
    const int lane = tid & 31;
    const int wm   = wid >> 1;          // 0..3 (M)
    const int wn   = wid & 1;           // 0..1 (N)
    const int laneR = lane >> 2;        // 0..7
    const int laneC = lane & 3;         // 0..3

    const int dir = blockIdx.z;
    const int n0  = blockIdx.x * 64;
    const int m0  = blockIdx.y * 128;
    const float* __restrict__ W    = dir ? Wb : Wf;
    const float* __restrict__ bias = dir ? bb : bf;
    float* __restrict__ out = &g_xproj[dir][0][0][0];

    const int arow = tid >> 1;               // 0..127
    const int acS  = (tid & 1) * 32;         // k base within 64-chunk
    const int brow = tid >> 2;               // 0..63
    const int bcS  = (tid & 3) * 16;
    const float* __restrict__ xr = x + (size_t)(m0 + arow) * I_ + acS;
    const float* __restrict__ wr = W + (size_t)(n0 + brow) * I_ + bcS;

    float acc[2][4][4];
#pragma unroll
    for (int mi = 0; mi < 2; mi++)
#pragma unroll
        for (int ni = 0; ni < 4; ni++)
#pragma unroll
            for (int q = 0; q < 4; q++) acc[mi][ni][q] = 0.f;

    float4 aR[8], bR[4];
#pragma unroll
    for (int i = 0; i < 8; i++) aR[i] = *(const float4*)(xr + i * 4);
#pragma unroll
    for (int i = 0; i < 4; i++) bR[i] = *(const float4*)(wr + i * 4);

    const int aBase = (wm * 32 + laneR) * APITCH + laneC * 4;
    const int bBase = (wn * 32 + laneR) * APITCH + laneC * 4;

    for (int st = 0; st < 8; st++) {
#pragma unroll
        for (int i = 0; i < 8; i++) {
            uint2 h, l; cvt_split(aR[i], h, l);
            int off = arow * APITCH + (acS + i * 4) * 2;
            *(uint2*)(Ahi + off) = h;
            *(uint2*)(Alo + off) = l;
        }
#pragma unroll
        for (int i = 0; i < 4; i++) {
            uint2 h, l; cvt_split(bR[i], h, l);
            int off = brow * APITCH + (bcS + i * 4) * 2;
            *(uint2*)(Bhi + off) = h;
            *(uint2*)(Blo + off) = l;
        }
        __syncthreads();

        if (st < 7) {  // prefetch next chunk under the MMAs
            const float* xr2 = xr + (st + 1) * 64;
            const float* wr2 = wr + (st + 1) * 64;
#pragma unroll
            for (int i = 0; i < 8; i++) aR[i] = *(const float4*)(xr2 + i * 4);
#pragma unroll
            for (int i = 0; i < 4; i++) bR[i] = *(const float4*)(wr2 + i * 4);
        }

#pragma unroll
        for (int kb = 0; kb < 64; kb += 16) {
            uint32_t bh[4][2], bl[4][2];
#pragma unroll
            for (int ni = 0; ni < 4; ni++) {
                int boff = bBase + ni * 8 * APITCH + kb * 2;
                bh[ni][0] = *(const uint32_t*)(Bhi + boff);
                bh[ni][1] = *(const uint32_t*)(Bhi + boff + 16);
                bl[ni][0] = *(const uint32_t*)(Blo + boff);
                bl[ni][1] = *(const uint32_t*)(Blo + boff + 16);
            }
#pragma unroll
            for (int mi = 0; mi < 2; mi++) {
                int aoff = aBase + mi * 16 * APITCH + kb * 2;
                uint32_t ah0 = *(const uint32_t*)(Ahi + aoff);
                uint32_t ah1 = *(const uint32_t*)(Ahi + aoff + 8 * APITCH);
                uint32_t ah2 = *(const uint32_t*)(Ahi + aoff + 16);
                uint32_t ah3 = *(const uint32_t*)(Ahi + aoff + 8 * APITCH + 16);
                uint32_t al0 = *(const uint32_t*)(Alo + aoff);
                uint32_t al1 = *(const uint32_t*)(Alo + aoff + 8 * APITCH);
                uint32_t al2 = *(const uint32_t*)(Alo + aoff + 16);
                uint32_t al3 = *(const uint32_t*)(Alo + aoff + 8 * APITCH + 16);
#pragma unroll
                for (int ni = 0; ni < 4; ni++) {
                    mma16816(acc[mi][ni], ah0, ah1, ah2, ah3, bh[ni][0], bh[ni][1]);
                    mma16816(acc[mi][ni], ah0, ah1, ah2, ah3, bl[ni][0], bl[ni][1]);
                    mma16816(acc[mi][ni], al0, al1, al2, al3, bh[ni][0], bh[ni][1]);
                }
            }
        }
        __syncthreads();
    }

#pragma unroll
    for (int mi = 0; mi < 2; mi++) {
#pragma unroll
        for (int ni = 0; ni < 4; ni++) {
            const int j = n0 + wn * 32 + ni * 8 + laneC * 2;
            float2 bv = *(const float2*)(bias + j);
            int m1 = m0 + wm * 32 + mi * 16 + laneR;
            int t1 = m1 & 511, b1 = m1 >> 9;
            float2 o1;
            o1.x = acc[mi][ni][0] + bv.x;
            o1.y = acc[mi][ni][1] + bv.y;
            *(float2*)(out + ((size_t)t1 * B_ + b1) * H_ + j) = o1;
            int m2 = m1 + 8;
            int t2 = m2 & 511, b2 = m2 >> 9;
            float2 o2;
            o2.x = acc[mi][ni][2] + bv.x;
            o2.y = acc[mi][ni][3] + bv.y;
            *(float2*)(out + ((size_t)t2 * B_ + b2) * H_ + j) = o2;
        }
    }
}

// ---------------- Phase 2: persistent recurrence (k-split, PROVEN in R1) ----
// 128 CTAs = 2 dirs x 8 batch-groups x 8 j-slice CTAs. Each CTA keeps a 64x512
// Wh slice transposed in SMEM + h state for 8 batches. Per step: k-split
// partial dot (16 warps) -> SMEM reduce -> tanh -> L2 h exchange + flag barrier.

#define SMEM_WHS   (512 * 65)                 // Whs_T[k][jj], pad 65
#define SMEM_HCUR  (8 * 512)
#define SMEM_RED   (16 * 512)
#define SMEM_FLOATS (SMEM_WHS + SMEM_HCUR + SMEM_RED)
#define SMEM_BYTES  (SMEM_FLOATS * 4)         // 182272 B

__global__ void __launch_bounds__(512, 1) rnn_kernel(
    const float* __restrict__ h0f, const float* __restrict__ h0b,
    const float* __restrict__ Whf, const float* __restrict__ Whb,
    float* __restrict__ y, float* __restrict__ hTf, float* __restrict__ hTb)
{
    extern __shared__ __align__(16) float smemf[];
    float* Whs  = smemf;                         // [512][65]
    float* hcur = smemf + SMEM_WHS;              // [8][512]
    float* red  = smemf + SMEM_WHS + SMEM_HCUR;  // [16][512]

    const int tid = threadIdx.x;
    const int c   = blockIdx.x & 7;       // j-slice cta within group
    const int grp = blockIdx.x >> 3;
    const int dir = grp >> 3;
    const int bg  = grp & 7;
    const int b0  = bg * 8;
    const int j0  = c * 64;

    const float* __restrict__ Wh = dir ? Whb : Whf;
    const float* __restrict__ h0 = dir ? h0b : h0f;
    const float* __restrict__ xp_base = &g_xproj[dir][0][0][0];
    float* __restrict__ hxd = &g_hx[dir][0][0][0];   // [2][64][512]
    int* flags = &g_flag[dir][bg][0];

    // monotonic flag base (flags persist across graph replays; validated R8)
    int base;
    asm volatile("ld.global.cg.u32 %0, [%1];" : "=r"(base) : "l"(&flags[c]));

    // Load Wh slice transposed: Whs[k*65 + jj] = Wh[j0+jj][k]
    for (int idx = tid; idx < 64 * 512; idx += 512) {
        int jj = idx >> 9;           // 0..63
        int k  = idx & 511;          // == tid
        Whs[k * 65 + jj] = Wh[(size_t)(j0 + jj) * H_ + k];
    }
    // Load initial h for our 8 batches
    {
        const float4* src = (const float4*)(h0 + (size_t)b0 * H_);
        float4* dst = (float4*)hcur;
        dst[tid]       = src[tid];
        dst[tid + 512] = src[tid + 512];
    }
    __syncthreads();

    const int lane = tid & 31;
    const int w    = tid >> 5;     // 16 warps, k-chunk of 32 each
    const int k0   = w * 32;
    const int pb   = tid >> 6;     // batch 0..7 for reduce/store
    const int pj   = tid & 63;     // local j 0..63

    for (int s = 0; s < T_; s++) {
        const int t = dir ? (T_ - 1 - s) : s;

        float acc0[8], acc1[8];
#pragma unroll
        for (int b = 0; b < 8; b++) { acc0[b] = 0.f; acc1[b] = 0.f; }

        const float4* h4 = (const float4*)hcur;
#pragma unroll
        for (int kb = 0; kb < 8; kb++) {
            const int kk = k0 + kb * 4;
            float wa0 = Whs[(kk + 0) * 65 + lane];
            float wa1 = Whs[(kk + 1) * 65 + lane];
            float wa2 = Whs[(kk + 2) * 65 + lane];
            float wa3 = Whs[(kk + 3) * 65 + lane];
            float wb0 = Whs[(kk + 0) * 65 + lane + 32];
            float wb1 = Whs[(kk + 1) * 65 + lane + 32];
            float wb2 = Whs[(kk + 2) * 65 + lane + 32];
            float wb3 = Whs[(kk + 3) * 65 + lane + 32];
#pragma unroll
            for (int b = 0; b < 8; b++) {
                float4 hv = h4[b * 128 + (kk >> 2)];   // broadcast across warp
                acc0[b] += hv.x * wa0; acc0[b] += hv.y * wa1;
                acc0[b] += hv.z * wa2; acc0[b] += hv.w * wa3;
                acc1[b] += hv.x * wb0; acc1[b] += hv.y * wb1;
                acc1[b] += hv.z * wb2; acc1[b] += hv.w * wb3;
            }
        }

        // start xp load early (L2 latency overlap with reduction)
        float xpv = xp_base[((size_t)t * B_ + b0 + pb) * H_ + j0 + pj];

#pragma unroll
        for (int b = 0; b < 8; b++) {
            red[w * 512 + b * 64 + lane]      = acc0[b];
            red[w * 512 + b * 64 + lane + 32] = acc1[b];
        }
        __syncthreads();

        float v = 0.f;
#pragma unroll
        for (int ww = 0; ww < 16; ww++) v += red[ww * 512 + tid];

        float hn = tanhf(xpv + v);

        const int p2 = (s + 1) & 1;
        y[((size_t)(b0 + pb) * T_ + t) * (2 * H_) + dir * H_ + j0 + pj] = hn;
        __stcg(&hxd[((size_t)p2 * B_ + b0 + pb) * H_ + j0 + pj], hn);
        if (s == T_ - 1) {
            (dir ? hTb : hTf)[(size_t)(b0 + pb) * H_ + j0 + pj] = hn;
        }

        __threadfence();
        __syncthreads();
        if (tid == 0) atomicExch(&flags[c], base + s + 1);

        if (tid < 8) {
            const int target = base + s + 1;
            int fv;
            do {
                asm volatile("ld.global.cg.u32 %0, [%1];" : "=r"(fv) : "l"(&flags[tid]));
                if (fv - target >= 0) break;
                __nanosleep(64);
            } while (true);
        }
        __syncthreads();

        // Reload full h for our 8 batches from the exchange buffer
        {
            const float4* src = (const float4*)&hxd[((size_t)p2 * B_ + b0) * H_];
            float4 v0 = __ldcg(&src[tid]);
            float4 v1 = __ldcg(&src[tid + 512]);
            float4* dst = (float4*)hcur;
            dst[tid]       = v0;
            dst[tid + 512] = v1;
        }
        __syncthreads();
    }
}

// ---------------- launch -----------------------------------------------------
extern "C" void kernel_launch(void* const* d_in, const int* in_sizes, int n_in,
                              void* d_out, int out_size)
{
    (void)in_sizes; (void)n_in; (void)out_size;
    const float* x   = (const float*)d_in[0];
    const float* h0f = (const float*)d_in[1];
    const float* h0b = (const float*)d_in[2];
    const float* Wxf = (const float*)d_in[3];
    const float* bxf = (const float*)d_in[4];
    const float* Whf = (const float*)d_in[5];
    const float* Wxb = (const float*)d_in[6];
    const float* bxb = (const float*)d_in[7];
    const float* Whb = (const float*)d_in[8];

    float* y   = (float*)d_out;                       // (B, T, 2H)
    float* hTf = y + (size_t)B_ * T_ * 2 * H_;        // (B, H)
    float* hTb = hTf + (size_t)B_ * H_;               // (B, H)

    cudaFuncSetAttribute(xproj_mma_kernel, cudaFuncAttributeMaxDynamicSharedMemorySize,
                         XP_SMEM);
    cudaFuncSetAttribute(rnn_kernel, cudaFuncAttributeMaxDynamicSharedMemorySize,
                         SMEM_BYTES);

    dim3 gg(8, 256, 2);   // N/64, M/128, dir
    xproj_mma_kernel<<<gg, 256, XP_SMEM>>>(x, Wxf, bxf, Wxb, bxb);

    rnn_kernel<<<128, 512, SMEM_BYTES>>>(h0f, h0b, Whf, Whb, y, hTf, hTb);
}